// round 14
// baseline (speedup 1.0000x reference)
#include <cuda_runtime.h>
#include <math.h>

// ---------------------------------------------------------------------------
// NeuralODE on GB300 (round 13): 3 CTAs/SM via register diet.
//  * 512 CTAs x 256 threads, RR=2, __launch_bounds__(256,3) -> 6 rows/SM
//  * W2 in regs (64; irreducible); W1/W3/base1/b2 in smem, 1-wavefront reads
//  * L2: warp = k-quarter (w>>1) x unit-half (w&1); lane covers 2 units
//    -> 8 uniform LDS.128 + 32 fma2 per row per thread (LDS halved vs r10)
//  * part[r][kq][u] stride-1; combine sums 4 partials + tanh
//  * rows counting-sorted, longest-first (LPT); pair skip by max tend
// ---------------------------------------------------------------------------

#define Bsz   1024
#define Tn    128
#define Dn    256
#define NACT  9
#define LATD  32
#define INW   43
#define RR    2
#define NCTA  512
#define NTH   256

typedef unsigned long long u64;

__device__ int g_perm[Bsz];

__device__ __forceinline__ u64 fma2(u64 a, u64 b, u64 c) {
    u64 d;
    asm("fma.rn.f32x2 %0, %1, %2, %3;" : "=l"(d) : "l"(a), "l"(b), "l"(c));
    return d;
}
__device__ __forceinline__ u64 add2(u64 a, u64 b) {
    u64 d;
    asm("add.rn.f32x2 %0, %1, %2;" : "=l"(d) : "l"(a), "l"(b));
    return d;
}
__device__ __forceinline__ float2 unpk(u64 v) {
    float2 f;
    asm("mov.b64 {%0, %1}, %2;" : "=f"(f.x), "=f"(f.y) : "l"(v));
    return f;
}
__device__ __forceinline__ float tanh_fast(float x) {
    float r;
    asm("tanh.approx.f32 %0, %1;" : "=f"(r) : "f"(x));
    return r;
}

// ---- counting sort of rows by length (stable, deterministic) --------------
__global__ void sort_kernel(const int* __restrict__ length)
{
    __shared__ int len_s[Bsz];
    __shared__ int hist[Tn];
    __shared__ int pref[Tn];
    const int tid = threadIdx.x;          // 128 threads
    for (int i = tid; i < Bsz; i += 128) {
        int v = length[i];
        len_s[i] = min(max(v, 0), Tn - 1);
    }
    if (tid < Tn) hist[tid] = 0;
    __syncthreads();
    for (int i = tid; i < Bsz; i += 128) atomicAdd(&hist[len_s[i]], 1);
    __syncthreads();
    if (tid == 0) {
        int acc = 0;
        for (int v = 0; v < Tn; v++) { pref[v] = acc; acc += hist[v]; }
    }
    __syncthreads();
    int pos = pref[tid];                  // thread tid handles bin value tid
    for (int b = 0; b < Bsz; b++)
        if (len_s[b] == tid) g_perm[pos++] = b;
}

struct __align__(16) Smem {
    float h1[RR][128];
    float h2[RR][128];
    float part[RR][4][128];   // [row][k-quarter][unit], stride-1 in unit
    float csr[RR][Dn];
    float W1T[11][128];       // [coef][unit]: 0-8 = state, 9 = t, 10 = c
    float base1s[RR][128];    // b1 + W1[:,9:41] @ latent, per row
    float W3s[NACT * 132];
    float b2s[128];
    float Yts[RR][12];
    float Ycur[RR][12];
    float ksum[RR][12];
    float b3s[16];
    float tsm[Tn];
    float tend[RR];
    float tendmax;
    int   brow[RR];
};

__global__ __launch_bounds__(NTH, 3)
void node_kernel(const float* __restrict__ ts, const float* __restrict__ y0,
                 const float* __restrict__ latent, const int* __restrict__ length,
                 const float* __restrict__ dense_ts, const float* __restrict__ dense_cs,
                 const float* __restrict__ W1, const float* __restrict__ b1,
                 const float* __restrict__ W2, const float* __restrict__ b2,
                 const float* __restrict__ W3, const float* __restrict__ b3,
                 float* __restrict__ out)
{
    __shared__ Smem s;
    const int tid = threadIdx.x;
    // longest-first launch: bid 0 = longest pair -> LPT under work-stealing
    const int grp = (NCTA - 1) - blockIdx.x;

    if (tid < RR) {
        int b = g_perm[grp * RR + tid];
        s.brow[tid] = b;
        s.tend[tid] = ts[max(length[b] - 1, 0)];
    }
    if (tid < Tn) s.tsm[tid] = ts[tid];
    if (tid < NACT) s.b3s[tid] = b3[tid];
    if (tid < 128) s.b2s[tid] = b2[tid];
    if (tid < RR * 12) {
        int r = tid / 12, d = tid % 12;
        s.Yts[r][d] = 0.f; s.Ycur[r][d] = 0.f; s.ksum[r][d] = 0.f;
    }
    __syncthreads();
    if (tid == 0) s.tendmax = fmaxf(s.tend[0], s.tend[1]);

    // ---- thread mappings --------------------------------------------------
    const int u1 = tid & 127;            // unit (layer-1 / combine)
    const int e  = tid >> 7;             // row
    const int w  = tid >> 5;
    const int l  = tid & 31;
    const int kq = w >> 1;               // k-quarter: k in [kq*32, kq*32+32)
    const int ua = (w & 1) * 64 + 2 * l; // units ua, ua+1

    // W2 slices: 2 units x 32 k = 64 floats as 32 u64 (the only big reg block)
    u64 W2A[16], W2B[16];
    {
        const u64* ga = reinterpret_cast<const u64*>(W2 + ua * 128 + kq * 32);
        const u64* gb = reinterpret_cast<const u64*>(W2 + (ua + 1) * 128 + kq * 32);
        #pragma unroll
        for (int m = 0; m < 16; m++) { W2A[m] = ga[m]; W2B[m] = gb[m]; }
    }

    // W1 transposed into smem: W1T[i][u] (stride-1 across lanes)
    for (int idx = tid; idx < 11 * 128; idx += NTH) {
        int i = idx >> 7, u = idx & 127;
        int col = (i < NACT) ? i : (i == 9 ? 41 : 42);
        s.W1T[i][u] = W1[u * INW + col];
    }
    // folded latent bias per (unit, row) into smem
    {
        const float* W1r = W1 + u1 * INW;
        const float* lv  = latent + g_perm[grp * RR + e] * LATD;
        float acc = b1[u1];
        #pragma unroll
        for (int li = 0; li < LATD; li++) acc = fmaf(W1r[9 + li], lv[li], acc);
        s.base1s[e][u1] = acc;
    }
    // W3 (padded rows)
    for (int idx = tid; idx < NACT * 128; idx += NTH)
        s.W3s[(idx >> 7) * 132 + (idx & 127)] = W3[idx];
    for (int idx = tid; idx < RR * Dn; idx += NTH) {
        int r = idx >> 8, d = idx & 255;
        s.csr[r][d] = dense_cs[s.brow[r] * Dn + d];
    }
    __syncthreads();
    if (tid < RR) {
        float y = y0[s.brow[tid]];
        s.Yts[tid][0] = y; s.Ycur[tid][0] = y;
        out[s.brow[tid] * Tn] = y;       // t = 0 sample
    }
    __syncthreads();

    // ---- time integration -------------------------------------------------
    for (int step = 0; step < Tn - 1; step++) {
        const float ta  = s.tsm[step];
        const float dtf = (s.tsm[step + 1] - ta) * 0.5f;
        if (ta <= s.tendmax) {
            for (int sub = 0; sub < 2; sub++) {
                const float t0 = ta + sub * dtf;
                for (int st = 0; st < 4; st++) {
                    const float t = t0 + ((st == 0) ? 0.f : (st == 3) ? dtf : 0.5f * dtf);

                    // ---- layer 1: 256 threads, one (unit,row) each ----
                    {
                        int ii = (int)ceilf(t);
                        ii = max(1, min(Dn - 1, ii));
                        float wc = t - (float)(ii - 1);
                        wc = fminf(fmaxf(wc, 0.f), 1.f);
                        float cl = s.csr[e][ii - 1];
                        float c  = fmaf(wc, s.csr[e][ii] - cl, cl);
                        float4 yA = *reinterpret_cast<const float4*>(&s.Yts[e][0]);
                        float4 yB = *reinterpret_cast<const float4*>(&s.Yts[e][4]);
                        float  y8 = s.Yts[e][8];
                        float a0 = s.base1s[e][u1];
                        float a1 = s.W1T[9][u1] * t;
                        a0 = fmaf(s.W1T[10][u1], c,    a0);
                        a1 = fmaf(s.W1T[0][u1],  yA.x, a1);
                        a0 = fmaf(s.W1T[1][u1],  yA.y, a0);
                        a1 = fmaf(s.W1T[2][u1],  yA.z, a1);
                        a0 = fmaf(s.W1T[3][u1],  yA.w, a0);
                        a1 = fmaf(s.W1T[4][u1],  yB.x, a1);
                        a0 = fmaf(s.W1T[5][u1],  yB.y, a0);
                        a1 = fmaf(s.W1T[6][u1],  yB.z, a1);
                        a0 = fmaf(s.W1T[7][u1],  yB.w, a0);
                        a1 = fmaf(s.W1T[8][u1],  y8,   a1);
                        s.h1[e][u1] = tanh_fast(a0 + a1);
                    }
                    __syncthreads();

                    // ---- layer 2: 2 units/lane, k-quarter/warp, uniform LDS
                    {
                        #pragma unroll
                        for (int r = 0; r < RR; r++) {
                            u64 aA0 = 0ull, aA1 = 0ull, aB0 = 0ull, aB1 = 0ull;
                            const ulonglong2* hb =
                                reinterpret_cast<const ulonglong2*>(&s.h1[r][kq * 32]);
                            #pragma unroll
                            for (int m = 0; m < 4; m++) {
                                ulonglong2 v = hb[m];        // warp-uniform: broadcast
                                aA0 = fma2(W2A[2 * m],     v.x, aA0);
                                aA1 = fma2(W2A[2 * m + 1], v.y, aA1);
                                aB0 = fma2(W2B[2 * m],     v.x, aB0);
                                aB1 = fma2(W2B[2 * m + 1], v.y, aB1);
                            }
                            #pragma unroll
                            for (int m = 4; m < 8; m++) {
                                ulonglong2 v = hb[m];
                                aA0 = fma2(W2A[2 * m],     v.x, aA0);
                                aA1 = fma2(W2A[2 * m + 1], v.y, aA1);
                                aB0 = fma2(W2B[2 * m],     v.x, aB0);
                                aB1 = fma2(W2B[2 * m + 1], v.y, aB1);
                            }
                            float2 fA = unpk(add2(aA0, aA1));
                            float2 fB = unpk(add2(aB0, aB1));
                            s.part[r][kq][ua]     = fA.x + fA.y;
                            s.part[r][kq][ua + 1] = fB.x + fB.y;
                        }
                    }
                    __syncthreads();

                    // ---- combine: h2 = tanh(sum of 4 k-quarter partials + b2)
                    {
                        float p = s.part[e][0][u1] + s.part[e][1][u1]
                                + s.part[e][2][u1] + s.part[e][3][u1];
                        s.h2[e][u1] = tanh_fast(p + s.b2s[u1]);
                    }
                    __syncthreads();

                    // ---- layer 3 + constraint + gating + RK bookkeeping ----
                    // 144 threads = warps 0-3 full + lanes 0..15 of warp 4
                    if (tid < 144) {
                        const unsigned mask = (tid < 128) ? 0xffffffffu : 0x0000ffffu;
                        const int q  = tid & 7;          // 16-k slice
                        const int r  = (tid >> 3) & 1;   // row
                        const int i3 = tid >> 4;         // output unit 0..8
                        const float4* wv = reinterpret_cast<const float4*>(&s.W3s[i3 * 132 + q * 16]);
                        const float4* hv = reinterpret_cast<const float4*>(&s.h2[r][q * 16]);
                        float ax = 0.f, ay = 0.f, az = 0.f, aw = 0.f;
                        #pragma unroll
                        for (int kk = 0; kk < 4; kk++) {
                            float4 a = wv[kk], b = hv[kk];
                            ax = fmaf(a.x, b.x, ax);
                            ay = fmaf(a.y, b.y, ay);
                            az = fmaf(a.z, b.z, az);
                            aw = fmaf(a.w, b.w, aw);
                        }
                        float acc = (ax + ay) + (az + aw);
                        acc += __shfl_xor_sync(mask, acc, 1);
                        acc += __shfl_xor_sync(mask, acc, 2);
                        acc += __shfl_xor_sync(mask, acc, 4);
                        if (q == 0) {
                            acc += s.b3s[i3];
                            if (i3 == 0) acc = -__cosf(acc);
                            if (t > s.tend[r]) acc = 0.f;     // per-sample stop
                            float ks;
                            if (st == 0) { ks = acc; s.ksum[r][i3] = ks; }
                            else {
                                ks = s.ksum[r][i3];
                                if (st < 3) { ks += 2.f * acc; s.ksum[r][i3] = ks; }
                            }
                            if (st < 3) {
                                float cY = (st == 2) ? dtf : 0.5f * dtf;
                                s.Yts[r][i3] = s.Ycur[r][i3] + cY * acc;
                            } else {
                                float y = s.Ycur[r][i3]
                                        + (dtf * (1.0f / 6.0f)) * (ks + acc);
                                s.Ycur[r][i3] = y;
                                s.Yts[r][i3]  = y;
                            }
                        }
                    }
                    __syncthreads();
                }
            }
        }
        if (tid < RR)
            out[s.brow[tid] * Tn + step + 1] = s.Ycur[tid][0];
    }
}

extern "C" void kernel_launch(void* const* d_in, const int* in_sizes, int n_in,
                              void* d_out, int out_size)
{
    (void)in_sizes; (void)n_in; (void)out_size;
    sort_kernel<<<1, 128>>>((const int*)d_in[3]);
    node_kernel<<<NCTA, NTH>>>(
        (const float*)d_in[0],   // ts
        (const float*)d_in[1],   // y0
        (const float*)d_in[2],   // latent_vec
        (const int*)  d_in[3],   // length
        (const float*)d_in[4],   // dense_ts (arange -> index math)
        (const float*)d_in[5],   // dense_cs
        (const float*)d_in[6],   // W1
        (const float*)d_in[7],   // b1
        (const float*)d_in[8],   // W2
        (const float*)d_in[9],   // b2
        (const float*)d_in[10],  // W3
        (const float*)d_in[11],  // b3
        (float*)d_out);
}